// round 10
// baseline (speedup 1.0000x reference)
#include <cuda_runtime.h>
#include <cstdint>

// USR_EMB: out[row] = emb[searchsorted(userlist, x[row])], 64 f32/row.
// FINAL (converged): ~98% of the HW-measured LTS cap (~6300 B/cyc -> ~11.3
// TB/s @NAT). 420MB must cross L2 (210MB L2-hit gathers + 210MB streaming
// writes); hard floor ~37us. Structures tried and rejected: deeper per-
// thread ILP (R5, -occ), smem staging + cp.async.bulk stores (R6, extra
// pass), block=512 (R8), unpredicated-store hoist (R9, tie). Best = R7:
//   - warp-cooperative indexing: lanes 0-15 compute 16 row indices via a
//     VERIFIED u+1 fast path (userlist = [-1,0..N-1]) with binary-search
//     fallback for generality; shfl-broadcast to all lanes.
//   - 8 rows/thread: burst of 8 independent .cg gathers (MLP=8, no L1
//     allocation — random reads over 25.6MB never hit 228KB L1),
//     then 8 coalesced .cs streaming stores (evict-first keeps the emb
//     table L2-resident under the 210MB write stream).

static constexpr int EMB = 64;
static constexpr int CPR = EMB / 4;  // 16 float4 chunks per row
static constexpr int RPW = 16;       // rows per warp

__global__ void __launch_bounds__(256) usr_emb_kernel(
    const int* __restrict__ x,
    const int* __restrict__ userlist,
    const float4* __restrict__ emb,      // [emb_rows][16] float4
    float4* __restrict__ out,            // [n_rows][16] float4
    int n_rows, int n_userlist, int emb_rows)
{
    int warpId = (blockIdx.x * blockDim.x + threadIdx.x) >> 5;
    int lane   = threadIdx.x & 31;
    int group  = lane >> 4;              // which 8-row half this thread moves
    int chunk  = lane & 15;              // float4 within row
    int wrow0  = warpId * RPW;
    if (wrow0 >= n_rows) return;

    // ---- Cooperative index computation: lanes 0-15, one row each ----
    int myIdx = 0;
    if (lane < RPW) {
        int r = wrow0 + lane;
        int u = (r < n_rows) ? __ldcs(&x[r]) : 0;   // coalesced 64B, read-once
        // Fast path: userlist = [-1, 0..N-1] => searchsorted(u) = u+1.
        // Verified against data; binary-search fallback for generality.
        int i = u + 1;
        bool ok = (i >= 1) && (i < n_userlist)
                  && (__ldg(&userlist[i]) == u)
                  && (__ldg(&userlist[i - 1]) < u);
        if (!ok) {
            int lo = 0, hi = n_userlist;
            while (lo < hi) {
                int mid = (lo + hi) >> 1;
                if (__ldg(&userlist[mid]) < u) lo = mid + 1; else hi = mid;
            }
            i = lo;
        }
        if (i >= emb_rows) i = emb_rows - 1;
        if (i < 0) i = 0;
        myIdx = i;
    }
    __syncwarp();

    // Each thread pulls its 8 row-indices from the computing lanes.
    int idx[8];
#pragma unroll
    for (int k = 0; k < 8; k++)
        idx[k] = __shfl_sync(0xffffffffu, myIdx, group * 8 + k);

    int rowBase = wrow0 + group * 8;

    // ---- 8 independent gathers in one burst (MLP=8), L2-hit, no L1 alloc --
    float4 v[8];
#pragma unroll
    for (int k = 0; k < 8; k++)
        v[k] = __ldcg(&emb[(size_t)idx[k] * CPR + chunk]);

    // ---- 8 coalesced streaming stores (evict-first; never re-read) ----
#pragma unroll
    for (int k = 0; k < 8; k++) {
        int r = rowBase + k;
        if (r < n_rows)
            __stcs(&out[(size_t)r * CPR + chunk], v[k]);
    }
}

extern "C" void kernel_launch(void* const* d_in, const int* in_sizes, int n_in,
                              void* d_out, int out_size)
{
    const int*   x        = (const int*)d_in[0];    // [B*H] int32
    const int*   userlist = (const int*)d_in[1];    // [N+1] int32
    const float* emb      = (const float*)d_in[2];  // [(N+1)*64] f32

    int n_rows     = in_sizes[0];          // 819200
    int n_userlist = in_sizes[1];          // 100001
    int emb_rows   = in_sizes[2] / EMB;    // 100001

    int n_warps = (n_rows + RPW - 1) / RPW;          // 51200
    long long total_threads = (long long)n_warps * 32;
    int block = 256;
    int grid  = (int)((total_threads + block - 1) / block);  // 6400

    usr_emb_kernel<<<grid, block>>>(x, userlist, (const float4*)emb,
                                    (float4*)d_out, n_rows, n_userlist, emb_rows);
}

// round 11
// speedup vs baseline: 1.0164x; 1.0164x over previous
#include <cuda_runtime.h>
#include <cstdint>

// USR_EMB: out[row] = emb[searchsorted(userlist, x[row])], 64 f32/row.
// At the LTS roofline (~420MB essential L2 traffic, ~11TB/s). R11 removes
// the last non-essential traffic: instead of 2 scattered probe loads PER
// ROW to verify idx=u+1, prove it structurally ONCE per warp with 2
// broadcast loads: userlist is sorted with all-distinct entries (problem
// semantics), so userlist[0]==-1 && userlist[N-1]==N-2 forces
// userlist == arange(-1,N-1), hence searchsorted(u)==clamp(u+1) for ALL u.
// Endpoint-check failure falls back to per-row binary search (generic).
// Rest = best-known R7 structure: warp-cooperative indexing, burst of 8
// .cg gathers (MLP=8, no L1 alloc), 8 coalesced .cs streaming stores.

static constexpr int EMB = 64;
static constexpr int CPR = EMB / 4;  // 16 float4 chunks per row
static constexpr int RPW = 16;       // rows per warp

__global__ void __launch_bounds__(256) usr_emb_kernel(
    const int* __restrict__ x,
    const int* __restrict__ userlist,
    const float4* __restrict__ emb,      // [emb_rows][16] float4
    float4* __restrict__ out,            // [n_rows][16] float4
    int n_rows, int n_userlist, int emb_rows)
{
    int warpId = (blockIdx.x * blockDim.x + threadIdx.x) >> 5;
    int lane   = threadIdx.x & 31;
    int group  = lane >> 4;              // which 8-row half this thread moves
    int chunk  = lane & 15;              // float4 within row
    int wrow0  = warpId * RPW;
    if (wrow0 >= n_rows) return;

    // ---- O(1) structural proof of the fast path (warp-uniform loads) ----
    // Sorted + all-distinct (problem semantics) + endpoints -1 and N-2
    // => userlist == arange(-1, N-1) => searchsorted(u) == clamp(u+1).
    bool fastOK = (__ldg(&userlist[0]) == -1) &&
                  (__ldg(&userlist[n_userlist - 1]) == n_userlist - 2);

    // ---- Cooperative index computation: lanes 0-15, one row each ----
    int myIdx = 0;
    if (lane < RPW) {
        int r = wrow0 + lane;
        int u = (r < n_rows) ? __ldcs(&x[r]) : 0;   // coalesced 64B, read-once
        int i;
        if (fastOK) {
            i = u + 1;                               // proven exact
        } else {
            // Generic lower_bound: first i with userlist[i] >= u.
            int lo = 0, hi = n_userlist;
            while (lo < hi) {
                int mid = (lo + hi) >> 1;
                if (__ldg(&userlist[mid]) < u) lo = mid + 1; else hi = mid;
            }
            i = lo;
        }
        // Clamp like jax's OOB-gather clamping (also covers u outside range).
        if (i >= emb_rows) i = emb_rows - 1;
        if (i < 0) i = 0;
        myIdx = i;
    }
    __syncwarp();

    // Each thread pulls its 8 row-indices from the computing lanes.
    int idx[8];
#pragma unroll
    for (int k = 0; k < 8; k++)
        idx[k] = __shfl_sync(0xffffffffu, myIdx, group * 8 + k);

    int rowBase = wrow0 + group * 8;

    // ---- 8 independent gathers in one burst (MLP=8), L2-hit, no L1 alloc --
    float4 v[8];
#pragma unroll
    for (int k = 0; k < 8; k++)
        v[k] = __ldcg(&emb[(size_t)idx[k] * CPR + chunk]);

    // ---- 8 coalesced streaming stores (evict-first; never re-read) ----
#pragma unroll
    for (int k = 0; k < 8; k++) {
        int r = rowBase + k;
        if (r < n_rows)
            __stcs(&out[(size_t)r * CPR + chunk], v[k]);
    }
}

extern "C" void kernel_launch(void* const* d_in, const int* in_sizes, int n_in,
                              void* d_out, int out_size)
{
    const int*   x        = (const int*)d_in[0];    // [B*H] int32
    const int*   userlist = (const int*)d_in[1];    // [N+1] int32
    const float* emb      = (const float*)d_in[2];  // [(N+1)*64] f32

    int n_rows     = in_sizes[0];          // 819200
    int n_userlist = in_sizes[1];          // 100001
    int emb_rows   = in_sizes[2] / EMB;    // 100001

    int n_warps = (n_rows + RPW - 1) / RPW;          // 51200
    long long total_threads = (long long)n_warps * 32;
    int block = 256;
    int grid  = (int)((total_threads + block - 1) / block);  // 6400

    usr_emb_kernel<<<grid, block>>>(x, userlist, (const float4*)emb,
                                    (float4*)d_out, n_rows, n_userlist, emb_rows);
}

// round 12
// speedup vs baseline: 1.0172x; 1.0008x over previous
#include <cuda_runtime.h>
#include <cstdint>

// USR_EMB: out[row] = emb[searchsorted(userlist, x[row])], 64 f32/row.
// FINAL (converged at the LTS roofline): 420MB of irreducible L2 crossings
// (210MB L2-hit gathers + 210MB streaming writes) at ~11.1TB/s ~= 98% of the
// HW-measured LTS cap (~6300 B/cyc @NAT). Hard floor ~37us; kernel ~37.8us.
//
// Design (survivors of R2-R11 ablations):
//  - O(1) structural fast-path proof, once per warp: userlist is sorted with
//    all-distinct entries (problem semantics), so endpoints -1 and N-2 force
//    userlist == arange(-1, N-1) => searchsorted(u) == clamp(u+1) for ALL u.
//    Two warp-uniform broadcast loads replace 2 scattered probes per row.
//    Endpoint mismatch => per-row binary search (fully generic).
//  - Warp-cooperative indexing: lanes 0-15 compute 16 row indices,
//    shfl-broadcast to all 32 lanes.
//  - 8 rows/thread: burst of 8 independent .cg gathers (MLP=8; no L1
//    allocation — random reads over 25.6MB never hit 228KB L1), then 8
//    unpredicated coalesced .cs streaming stores (evict-first keeps the
//    emb table L2-resident under the 210MB write stream).
// Rejected: deeper ILP (R5: -occ), smem staging + cp.async.bulk (R6: extra
// pass + sync), block=512 (R8: -occ).

static constexpr int EMB = 64;
static constexpr int CPR = EMB / 4;  // 16 float4 chunks per row
static constexpr int RPW = 16;       // rows per warp

__global__ void __launch_bounds__(256) usr_emb_kernel(
    const int* __restrict__ x,
    const int* __restrict__ userlist,
    const float4* __restrict__ emb,      // [emb_rows][16] float4
    float4* __restrict__ out,            // [n_rows][16] float4
    int n_rows, int n_userlist, int emb_rows)
{
    int warpId = (blockIdx.x * blockDim.x + threadIdx.x) >> 5;
    int lane   = threadIdx.x & 31;
    int group  = lane >> 4;              // which 8-row half this thread moves
    int chunk  = lane & 15;              // float4 within row
    int wrow0  = warpId * RPW;
    if (wrow0 >= n_rows) return;

    bool full = (wrow0 + RPW) <= n_rows;

    // ---- O(1) structural proof of the fast path (warp-uniform loads) ----
    bool fastOK = (__ldg(&userlist[0]) == -1) &&
                  (__ldg(&userlist[n_userlist - 1]) == n_userlist - 2);

    // ---- Cooperative index computation: lanes 0-15, one row each ----
    int myIdx = 0;
    if (lane < RPW) {
        int r = wrow0 + lane;
        int u = (full || r < n_rows) ? __ldcs(&x[r]) : 0;  // coalesced 64B
        int i;
        if (fastOK) {
            i = u + 1;                               // proven exact
        } else {
            // Generic lower_bound: first i with userlist[i] >= u.
            int lo = 0, hi = n_userlist;
            while (lo < hi) {
                int mid = (lo + hi) >> 1;
                if (__ldg(&userlist[mid]) < u) lo = mid + 1; else hi = mid;
            }
            i = lo;
        }
        // Clamp like jax's OOB-gather clamping (covers u outside range).
        if (i >= emb_rows) i = emb_rows - 1;
        if (i < 0) i = 0;
        myIdx = i;
    }

    // Full-mask shfl_sync converges the warp.
    int idx[8];
#pragma unroll
    for (int k = 0; k < 8; k++)
        idx[k] = __shfl_sync(0xffffffffu, myIdx, group * 8 + k);

    int rowBase = wrow0 + group * 8;

    if (full) {
        // ---- 8 independent gathers in one burst (MLP=8), L2-hit, no L1 ----
        float4 v[8];
#pragma unroll
        for (int k = 0; k < 8; k++)
            v[k] = __ldcg(&emb[(size_t)idx[k] * CPR + chunk]);

        // ---- 8 unpredicated coalesced streaming stores ----
#pragma unroll
        for (int k = 0; k < 8; k++)
            __stcs(&out[(size_t)(rowBase + k) * CPR + chunk], v[k]);
    } else {
        // Guarded tail path (generic shapes).
#pragma unroll
        for (int k = 0; k < 8; k++) {
            int r = rowBase + k;
            if (r < n_rows) {
                float4 v = __ldcg(&emb[(size_t)idx[k] * CPR + chunk]);
                __stcs(&out[(size_t)r * CPR + chunk], v);
            }
        }
    }
}

extern "C" void kernel_launch(void* const* d_in, const int* in_sizes, int n_in,
                              void* d_out, int out_size)
{
    const int*   x        = (const int*)d_in[0];    // [B*H] int32
    const int*   userlist = (const int*)d_in[1];    // [N+1] int32
    const float* emb      = (const float*)d_in[2];  // [(N+1)*64] f32

    int n_rows     = in_sizes[0];          // 819200
    int n_userlist = in_sizes[1];          // 100001
    int emb_rows   = in_sizes[2] / EMB;    // 100001

    int n_warps = (n_rows + RPW - 1) / RPW;          // 51200
    long long total_threads = (long long)n_warps * 32;
    int block = 256;
    int grid  = (int)((total_threads + block - 1) / block);  // 6400

    usr_emb_kernel<<<grid, block>>>(x, userlist, (const float4*)emb,
                                    (float4*)d_out, n_rows, n_userlist, emb_rows);
}